// round 2
// baseline (speedup 1.0000x reference)
#include <cuda_runtime.h>
#include <math.h>

#define BB 2
#define SS 2048
#define DD 1024
#define HH 16
#define DHH 64

// ---------------- scratch (device globals; no allocation allowed) ----------------
__device__ float g_qh[BB*HH*SS*DHH];     // [B,H,S,DH]
__device__ float g_kh[BB*HH*SS*DHH];     // [B,H,S,DH]
__device__ float g_vproj[BB*SS*DHH];     // [B,S,DH]
__device__ float g_oh[BB*HH*SS*DHH];     // per-head attention outputs
__device__ float g_mean[BB*SS*DHH];      // head-mean
__device__ float g_m[BB*HH*SS];          // row max
__device__ float g_l[BB*HH*SS];          // row sumexp

// ---------------- kernel 1: projections (33 GEMM tasks) ----------------
// C[s,e] = sum_d X[s,d] * W[e,d] + bias[e];  M=2048, N=64, K=1024
__global__ __launch_bounds__(256) void proj_kernel(
    const float* __restrict__ q, const float* __restrict__ k, const float* __restrict__ v,
    const float* __restrict__ Wq, const float* __restrict__ bq,
    const float* __restrict__ Wk, const float* __restrict__ bk,
    const float* __restrict__ Wv, const float* __restrict__ bv)
{
    __shared__ float xs[32][68];   // xs[d][s] (transposed X tile)
    __shared__ float wsm[32][68];  // wsm[d][e] (transposed W tile)

    int task = blockIdx.z;
    int b = blockIdx.y;
    int s0 = blockIdx.x * 64;

    const float* X; const float* W; const float* bias; float* out;
    if (task < HH) {
        X = q + (size_t)b*SS*DD; W = Wq + (size_t)task*DHH*DD; bias = bq + task*DHH;
        out = g_qh + ((size_t)(b*HH + task) * SS) * DHH;
    } else if (task < 2*HH) {
        int h = task - HH;
        X = k + (size_t)b*SS*DD; W = Wk + (size_t)h*DHH*DD; bias = bk + h*DHH;
        out = g_kh + ((size_t)(b*HH + h) * SS) * DHH;
    } else {
        X = v + (size_t)b*SS*DD; W = Wv; bias = bv;
        out = g_vproj + (size_t)b*SS*DHH;
    }

    int tid = threadIdx.x;
    int ty = tid >> 4, tx = tid & 15;
    int lr = tid >> 2;            // 0..63
    int ld = (tid & 3) * 8;       // 0,8,16,24

    float acc[4][4];
    #pragma unroll
    for (int i = 0; i < 4; i++)
        #pragma unroll
        for (int j = 0; j < 4; j++) acc[i][j] = 0.f;

    for (int d0 = 0; d0 < DD; d0 += 32) {
        float4 xa = *(const float4*)&X[(size_t)(s0+lr)*DD + d0 + ld];
        float4 xb = *(const float4*)&X[(size_t)(s0+lr)*DD + d0 + ld + 4];
        float4 wa = *(const float4*)&W[(size_t)lr*DD + d0 + ld];
        float4 wb = *(const float4*)&W[(size_t)lr*DD + d0 + ld + 4];
        __syncthreads();
        xs[ld+0][lr]=xa.x; xs[ld+1][lr]=xa.y; xs[ld+2][lr]=xa.z; xs[ld+3][lr]=xa.w;
        xs[ld+4][lr]=xb.x; xs[ld+5][lr]=xb.y; xs[ld+6][lr]=xb.z; xs[ld+7][lr]=xb.w;
        wsm[ld+0][lr]=wa.x; wsm[ld+1][lr]=wa.y; wsm[ld+2][lr]=wa.z; wsm[ld+3][lr]=wa.w;
        wsm[ld+4][lr]=wb.x; wsm[ld+5][lr]=wb.y; wsm[ld+6][lr]=wb.z; wsm[ld+7][lr]=wb.w;
        __syncthreads();
        #pragma unroll 8
        for (int kk = 0; kk < 32; kk++) {
            float4 xf = *(const float4*)&xs[kk][ty*4];
            float4 wf = *(const float4*)&wsm[kk][tx*4];
            float xr[4] = {xf.x, xf.y, xf.z, xf.w};
            float wr[4] = {wf.x, wf.y, wf.z, wf.w};
            #pragma unroll
            for (int i = 0; i < 4; i++)
                #pragma unroll
                for (int j = 0; j < 4; j++)
                    acc[i][j] += xr[i] * wr[j];
        }
    }

    float4 b4 = *(const float4*)&bias[tx*4];
    float br[4] = {b4.x, b4.y, b4.z, b4.w};
    #pragma unroll
    for (int i = 0; i < 4; i++) {
        float4 o;
        o.x = acc[i][0] + br[0]; o.y = acc[i][1] + br[1];
        o.z = acc[i][2] + br[2]; o.w = acc[i][3] + br[3];
        *(float4*)&out[(size_t)(s0 + ty*4 + i)*DHH + tx*4] = o;
    }
}

// ---------------- kernel 2: attention (raw scores out + online softmax + PV) ----------------
#define ST 68
__global__ __launch_bounds__(256) void attn_kernel(float* __restrict__ attn_out)
{
    extern __shared__ float sm[];
    float* qs = sm;               // qs[e*ST + r]
    float* ks = sm + 64*ST;       // ks[e*ST + c]
    float* vs = sm + 2*64*ST;     // vs[c*ST + e]
    float* ps = sm + 3*64*ST;     // ps[c*ST + r]

    int qi = (int)(gridDim.x - 1 - blockIdx.x);   // big tiles first (wave balance)
    int h = blockIdx.y, b = blockIdx.z;
    int s0 = qi * 64;
    int tid = threadIdx.x;
    int ty = tid >> 4, tx = tid & 15;
    int lr = tid >> 2;            // 0..63
    int le = (tid & 3) * 16;      // 0,16,32,48

    size_t bh = (size_t)(b*HH + h);
    const float* Q  = g_qh + bh * SS * DHH;
    const float* Kp = g_kh + bh * SS * DHH;
    const float* V  = g_vproj + (size_t)b * SS * DHH;

    // load Q tile transposed
    #pragma unroll
    for (int i = 0; i < 16; i += 4) {
        float4 f = *(const float4*)&Q[(size_t)(s0+lr)*DHH + le + i];
        qs[(le+i+0)*ST + lr] = f.x;
        qs[(le+i+1)*ST + lr] = f.y;
        qs[(le+i+2)*ST + lr] = f.z;
        qs[(le+i+3)*ST + lr] = f.w;
    }

    float m_run[4], l_run[4], acc[4][4];
    int srow[4];
    #pragma unroll
    for (int i = 0; i < 4; i++) {
        m_run[i] = -INFINITY; l_run[i] = 0.f;
        srow[i] = s0 + ty*4 + i;
        #pragma unroll
        for (int j = 0; j < 4; j++) acc[i][j] = 0.f;
    }

    for (int j = 0; j <= qi; j++) {
        int t0 = j * 64;
        __syncthreads();   // previous PV / Q load complete before overwrite
        #pragma unroll
        for (int i = 0; i < 16; i += 4) {
            float4 f = *(const float4*)&Kp[(size_t)(t0+lr)*DHH + le + i];
            ks[(le+i+0)*ST + lr] = f.x;
            ks[(le+i+1)*ST + lr] = f.y;
            ks[(le+i+2)*ST + lr] = f.z;
            ks[(le+i+3)*ST + lr] = f.w;
            float4 g = *(const float4*)&V[(size_t)(t0+lr)*DHH + le + i];
            *(float4*)&vs[lr*ST + le + i] = g;
        }
        __syncthreads();

        float sreg[4][4];
        #pragma unroll
        for (int i = 0; i < 4; i++)
            #pragma unroll
            for (int jj = 0; jj < 4; jj++) sreg[i][jj] = 0.f;

        #pragma unroll 16
        for (int e = 0; e < 64; e++) {
            float4 qf = *(const float4*)&qs[e*ST + ty*4];
            float4 kf = *(const float4*)&ks[e*ST + tx*4];
            float qr[4] = {qf.x, qf.y, qf.z, qf.w};
            float kr[4] = {kf.x, kf.y, kf.z, kf.w};
            #pragma unroll
            for (int i = 0; i < 4; i++)
                #pragma unroll
                for (int jj = 0; jj < 4; jj++)
                    sreg[i][jj] += qr[i] * kr[jj];
        }

        bool diag = (j == qi);
        #pragma unroll
        for (int i = 0; i < 4; i++) {
            #pragma unroll
            for (int jj = 0; jj < 4; jj++) sreg[i][jj] *= 0.125f;  // 1/sqrt(64)

            // raw (unnormalized) score write; norm pass fixes it up
            float4 w;
            w.x = sreg[i][0]; w.y = sreg[i][1]; w.z = sreg[i][2]; w.w = sreg[i][3];
            *(float4*)&attn_out[(((size_t)b*SS + srow[i])*HH + h)*SS + t0 + tx*4] = w;

            bool vld[4];
            #pragma unroll
            for (int jj = 0; jj < 4; jj++)
                vld[jj] = (!diag) || (t0 + tx*4 + jj <= srow[i]);

            float mx = -INFINITY;
            #pragma unroll
            for (int jj = 0; jj < 4; jj++) if (vld[jj]) mx = fmaxf(mx, sreg[i][jj]);
            #pragma unroll
            for (int off = 8; off > 0; off >>= 1)
                mx = fmaxf(mx, __shfl_xor_sync(0xffffffffu, mx, off, 16));

            float mnew = fmaxf(m_run[i], mx);
            float fac = expf(m_run[i] - mnew);
            m_run[i] = mnew;

            float psum = 0.f;
            float pv[4];
            #pragma unroll
            for (int jj = 0; jj < 4; jj++) {
                pv[jj] = vld[jj] ? expf(sreg[i][jj] - mnew) : 0.f;
                psum += pv[jj];
            }
            #pragma unroll
            for (int off = 8; off > 0; off >>= 1)
                psum += __shfl_xor_sync(0xffffffffu, psum, off, 16);
            l_run[i] = l_run[i] * fac + psum;

            #pragma unroll
            for (int jj = 0; jj < 4; jj++) acc[i][jj] *= fac;
            #pragma unroll
            for (int jj = 0; jj < 4; jj++)
                ps[(tx*4+jj)*ST + ty*4 + i] = pv[jj];
        }
        __syncthreads();

        #pragma unroll 16
        for (int c = 0; c < 64; c++) {
            float4 pf = *(const float4*)&ps[c*ST + ty*4];
            float4 vf = *(const float4*)&vs[c*ST + tx*4];
            float pr[4] = {pf.x, pf.y, pf.z, pf.w};
            float vr[4] = {vf.x, vf.y, vf.z, vf.w};
            #pragma unroll
            for (int i = 0; i < 4; i++)
                #pragma unroll
                for (int jj = 0; jj < 4; jj++)
                    acc[i][jj] += pr[i] * vr[jj];
        }
    }

    float* Oh = g_oh + bh * SS * DHH;
    #pragma unroll
    for (int i = 0; i < 4; i++) {
        float linv = 1.f / l_run[i];
        float4 o;
        o.x = acc[i][0]*linv; o.y = acc[i][1]*linv;
        o.z = acc[i][2]*linv; o.w = acc[i][3]*linv;
        *(float4*)&Oh[(size_t)srow[i]*DHH + tx*4] = o;
    }
    if (tx == 0) {
        #pragma unroll
        for (int i = 0; i < 4; i++) {
            g_m[bh*SS + srow[i]] = m_run[i];
            g_l[bh*SS + srow[i]] = l_run[i];
        }
    }
}

// ---------------- kernel 3: normalize raw scores -> probabilities, zero masked ----------------
__global__ __launch_bounds__(256) void norm_kernel(float* __restrict__ attn)
{
    int row = blockIdx.x;                 // 0..B*S*H-1
    int h = row % HH;
    int s = (row / HH) % SS;
    int b = row / (HH * SS);
    size_t base = (size_t)row * SS;
    int mi = (b*HH + h)*SS + s;
    float m = g_m[mi];
    float linv = 1.f / g_l[mi];

    int tid = threadIdx.x;
    #pragma unroll
    for (int i = 0; i < 2; i++) {
        int t0 = (tid + i*256) * 4;
        float4* p = (float4*)&attn[base + t0];
        float4 r;
        if (t0 + 3 <= s) {
            r = *p;
            r.x = expf(r.x - m) * linv;
            r.y = expf(r.y - m) * linv;
            r.z = expf(r.z - m) * linv;
            r.w = expf(r.w - m) * linv;
        } else if (t0 > s) {
            r.x = 0.f; r.y = 0.f; r.z = 0.f; r.w = 0.f;
        } else {
            r = *p;
            r.x = (t0+0 <= s) ? expf(r.x - m) * linv : 0.f;
            r.y = (t0+1 <= s) ? expf(r.y - m) * linv : 0.f;
            r.z = (t0+2 <= s) ? expf(r.z - m) * linv : 0.f;
            r.w = (t0+3 <= s) ? expf(r.w - m) * linv : 0.f;
        }
        *p = r;
    }
}

// ---------------- kernel 4: mean over heads ----------------
__global__ __launch_bounds__(256) void mean_kernel()
{
    int idx = blockIdx.x * 256 + threadIdx.x;   // < B*S*DH
    int e = idx & 63;
    int s = (idx >> 6) & (SS - 1);
    int b = idx >> 17;                          // 6 + 11
    float sum = 0.f;
    #pragma unroll
    for (int h = 0; h < HH; h++)
        sum += g_oh[((size_t)(b*HH + h)*SS + s)*DHH + e];
    g_mean[idx] = sum * (1.f / 16.f);
}

// ---------------- kernel 5: output projection with Wo ----------------
// out[s,d] = sum_e mean[s,e] * Wo[d,e];  M=2048, N=1024, K=64
__global__ __launch_bounds__(256) void outproj_kernel(const float* __restrict__ Wo,
                                                      float* __restrict__ out)
{
    __shared__ float ms[64][68];   // ms[e][r]
    __shared__ float wsm[64][68];  // wsm[e][c]
    int s0 = blockIdx.x * 64, d0 = blockIdx.y * 64, b = blockIdx.z;
    int tid = threadIdx.x;
    int ty = tid >> 4, tx = tid & 15;
    int lr = tid >> 2;
    int le = (tid & 3) * 16;

    #pragma unroll
    for (int i = 0; i < 16; i += 4) {
        float4 f = *(const float4*)&g_mean[((size_t)b*SS + s0+lr)*DHH + le + i];
        ms[le+i+0][lr] = f.x; ms[le+i+1][lr] = f.y;
        ms[le+i+2][lr] = f.z; ms[le+i+3][lr] = f.w;
        float4 g = *(const float4*)&Wo[(size_t)(d0+lr)*DHH + le + i];
        wsm[le+i+0][lr] = g.x; wsm[le+i+1][lr] = g.y;
        wsm[le+i+2][lr] = g.z; wsm[le+i+3][lr] = g.w;
    }
    __syncthreads();

    float acc[4][4];
    #pragma unroll
    for (int i = 0; i < 4; i++)
        #pragma unroll
        for (int j = 0; j < 4; j++) acc[i][j] = 0.f;

    #pragma unroll 16
    for (int e = 0; e < 64; e++) {
        float4 mf = *(const float4*)&ms[e][ty*4];
        float4 wf = *(const float4*)&wsm[e][tx*4];
        float mr[4] = {mf.x, mf.y, mf.z, mf.w};
        float wr[4] = {wf.x, wf.y, wf.z, wf.w};
        #pragma unroll
        for (int i = 0; i < 4; i++)
            #pragma unroll
            for (int j = 0; j < 4; j++)
                acc[i][j] += mr[i] * wr[j];
    }

    #pragma unroll
    for (int i = 0; i < 4; i++) {
        float4 o;
        o.x = acc[i][0]; o.y = acc[i][1]; o.z = acc[i][2]; o.w = acc[i][3];
        *(float4*)&out[(size_t)b*SS*DD + (size_t)(s0 + ty*4 + i)*DD + d0 + tx*4] = o;
    }
}

// ---------------- launch ----------------
extern "C" void kernel_launch(void* const* d_in, const int* in_sizes, int n_in,
                              void* d_out, int out_size)
{
    (void)in_sizes; (void)n_in; (void)out_size;
    const float* q  = (const float*)d_in[0];
    const float* k  = (const float*)d_in[1];
    const float* v  = (const float*)d_in[2];
    // d_in[3] = mask (causal, computed analytically; unused)
    const float* Wv = (const float*)d_in[4];
    const float* bv = (const float*)d_in[5];
    const float* Wq = (const float*)d_in[6];
    const float* bq = (const float*)d_in[7];
    const float* Wk = (const float*)d_in[8];
    const float* bk = (const float*)d_in[9];
    const float* Wo = (const float*)d_in[10];

    float* out  = (float*)d_out;
    float* attn = out + (size_t)BB*SS*DD;   // [B,S,H,S] after [B,S,D]

    const int attn_smem = 4 * 64 * ST * (int)sizeof(float);  // 69632 B
    cudaFuncSetAttribute(attn_kernel, cudaFuncAttributeMaxDynamicSharedMemorySize, attn_smem);

    proj_kernel<<<dim3(SS/64, BB, 2*HH + 1), 256>>>(q, k, v, Wq, bq, Wk, bk, Wv, bv);
    attn_kernel<<<dim3(SS/64, HH, BB), 256, attn_smem>>>(attn);
    norm_kernel<<<BB*SS*HH, 256>>>(attn);
    mean_kernel<<<BB*SS*DHH/256, 256>>>();
    outproj_kernel<<<dim3(SS/64, DD/64, BB), 256>>>(Wo, out);
}